// round 6
// baseline (speedup 1.0000x reference)
#include <cuda_runtime.h>
#include <cstdint>
#include <cfloat>

// Problem constants
#define N_PIX   16777216          // 16 * 1 * 1024 * 1024
#define NF4     4194304           // N_PIX / 4
#define RED_B   2048              // reduction blocks
#define BINS    256
#define TILES   1024              // 16 images * 8 * 8
#define CLIPV   2560.0f           // max(int(40.0*16384//256),1)

// Scratch (device globals only — no allocations allowed)
__device__ float         g_pmin[RED_B];
__device__ float         g_pmax[RED_B];
__device__ double        g_psum[RED_B];
__device__ double        g_psq [RED_B];
__device__ float         g_AB[2];
__device__ unsigned char g_bidx[N_PIX];
__device__ unsigned char g_lut8[TILES * BINS];   // LUT values are exact ints 0..255

// ---------------------------------------------------------------------------
// Kernel 1: partial min/max/sum/sumsq. 2048 blocks x 256 threads, 32 elems/thr.
// ---------------------------------------------------------------------------
__global__ void __launch_bounds__(256) k_reduce(const float4* __restrict__ x)
{
    int tid = threadIdx.x;
    int t   = blockIdx.x * 256 + tid;

    float mn =  FLT_MAX, mx = -FLT_MAX;
    float s = 0.0f, q = 0.0f;
#pragma unroll
    for (int i = 0; i < 8; i++) {
        float4 v = x[t + i * (RED_B * 256)];
        mn = fminf(mn, fminf(fminf(v.x, v.y), fminf(v.z, v.w)));
        mx = fmaxf(mx, fmaxf(fmaxf(v.x, v.y), fmaxf(v.z, v.w)));
        s += (v.x + v.y) + (v.z + v.w);
        q += (v.x * v.x + v.y * v.y) + (v.z * v.z + v.w * v.w);
    }

    __shared__ float  smn[256], smx[256];
    __shared__ double ss[256], sq[256];
    smn[tid] = mn; smx[tid] = mx;
    ss[tid] = (double)s; sq[tid] = (double)q;
    __syncthreads();
    for (int o = 128; o > 0; o >>= 1) {
        if (tid < o) {
            smn[tid] = fminf(smn[tid], smn[tid + o]);
            smx[tid] = fmaxf(smx[tid], smx[tid + o]);
            ss[tid] += ss[tid + o];
            sq[tid] += sq[tid + o];
        }
        __syncthreads();
    }
    if (tid == 0) {
        g_pmin[blockIdx.x] = smn[0];
        g_pmax[blockIdx.x] = smx[0];
        g_psum[blockIdx.x] = ss[0];
        g_psq [blockIdx.x] = sq[0];
    }
}

// ---------------------------------------------------------------------------
// Kernel 2: final reduce (2048 partials) + affine constants (fp64 replica of
// the reference's normalize -> standardize -> normalize chain -> x*A+B)
// ---------------------------------------------------------------------------
__global__ void __launch_bounds__(1024) k_finalize()
{
    int tid = threadIdx.x;
    __shared__ float  smn[1024], smx[1024];
    __shared__ double ss[1024], sq[1024];
    smn[tid] = fminf(g_pmin[tid], g_pmin[tid + 1024]);
    smx[tid] = fmaxf(g_pmax[tid], g_pmax[tid + 1024]);
    ss[tid]  = g_psum[tid] + g_psum[tid + 1024];
    sq[tid]  = g_psq[tid]  + g_psq[tid + 1024];
    __syncthreads();
    for (int o = 512; o > 0; o >>= 1) {
        if (tid < o) {
            smn[tid] = fminf(smn[tid], smn[tid + o]);
            smx[tid] = fmaxf(smx[tid], smx[tid + o]);
            ss[tid] += ss[tid + o];
            sq[tid] += sq[tid + o];
        }
        __syncthreads();
    }
    if (tid == 0) {
        double mn = (double)smn[0];
        double mx = (double)smx[0];
        double span = mx - mn;
        const double N = (double)N_PIX;
        double S = ss[0], Q = sq[0];
        double meanx = S / N;
        double varx  = (Q - S * S / N) / (N - 1.0);
        double mean1 = (meanx - mn) / span;
        double std1  = sqrt(varx) / span;
        double zmin  = (0.0 - mean1) / std1;
        double zmax  = (1.0 - mean1) / std1;
        double zspan = zmax - zmin;
        double A = 1.0 / (span * std1 * zspan);
        double B = (((0.0 - mn) / span - mean1) / std1 - zmin) / zspan;
        g_AB[0] = (float)A;
        g_AB[1] = (float)B;
    }
}

// ---------------------------------------------------------------------------
// Kernel 3: one 512-thread block per 128x128 tile. 16 warp-private
// sub-histograms + bidx store, then clip -> scan -> residual -> LUT in-block.
// ---------------------------------------------------------------------------
__global__ void __launch_bounds__(512) k_hist(const float* __restrict__ x)
{
    __shared__ unsigned int h[16][BINS];
    __shared__ float        cs[BINS];

    int t   = blockIdx.x;          // tile id: ((bc*8)+ti)*8+tj
    int tid = threadIdx.x;
#pragma unroll
    for (int k = tid >> 8; k < 16; k += 2) h[k][tid & 255] = 0;
    __syncthreads();

    float A = g_AB[0], B = g_AB[1];

    int bc = t >> 6;
    int ti = (t >> 3) & 7;
    int tj = t & 7;
    int row0 = ti * 128;
    int col0 = tj * 128;
    int wsub = tid >> 5;           // warp-private sub-histogram (0..15)

    const float4* xp = (const float4*)(x + ((size_t)bc << 20));
    uchar4*       bp = (uchar4*)(g_bidx + ((size_t)bc << 20));

#pragma unroll
    for (int it = 0; it < 8; it++) {
        int row   = row0 + it * 16 + (tid >> 5);
        int cidx4 = (row << 8) + (col0 >> 2) + (tid & 31);  // float4 index
        float4 v  = xp[cidx4];
        int b0 = min(max((int)(fmaf(v.x, A, B) * 256.0f), 0), 255);
        int b1 = min(max((int)(fmaf(v.y, A, B) * 256.0f), 0), 255);
        int b2 = min(max((int)(fmaf(v.z, A, B) * 256.0f), 0), 255);
        int b3 = min(max((int)(fmaf(v.w, A, B) * 256.0f), 0), 255);
        atomicAdd(&h[wsub][b0], 1u);
        atomicAdd(&h[wsub][b1], 1u);
        atomicAdd(&h[wsub][b2], 1u);
        atomicAdd(&h[wsub][b3], 1u);
        bp[cidx4] = make_uchar4((unsigned char)b0, (unsigned char)b1,
                                (unsigned char)b2, (unsigned char)b3);
    }
    __syncthreads();

    // threads 0..255 do the clip + scan + LUT; all threads hit the barriers
    float v = 0.0f;
    if (tid < 256) {
        unsigned int hv = 0;
#pragma unroll
        for (int k = 0; k < 16; k++) hv += h[k][tid];
        v = fminf((float)hv, CLIPV);
        cs[tid] = v;
    }
    __syncthreads();
#pragma unroll
    for (int off = 1; off < BINS; off <<= 1) {
        float add = (tid < 256 && tid >= off) ? cs[tid - off] : 0.0f;
        __syncthreads();
        if (tid < 256) cs[tid] += add;
        __syncthreads();
    }
    if (tid < 256) {
        float total = cs[BINS - 1];
        float resid = (16384.0f - total) * (1.0f / 256.0f);
        float lv = (cs[tid] + (float)(tid + 1) * resid) * (255.0f / 16384.0f);
        lv = floorf(fminf(fmaxf(lv, 0.0f), 255.0f));
        g_lut8[t * BINS + tid] = (unsigned char)lv;
    }
}

// ---------------------------------------------------------------------------
// Kernel 4: bilinear LUT apply — ONE LDS.32 per pixel. Grid 2048 blocks
// (image, 8-row segment) x 256 threads; i0/i1 constant per 64-row band.
// slut[(j0,bin)] packs uchar4(v00, v10, v01, v11), j1=min(j0+1,7) folded in.
// Output stored with __stcs (streaming) to preserve L2 for bidx/lut.
// ---------------------------------------------------------------------------
__device__ __forceinline__ float u8f(unsigned int packed, int sel)
{
    // byte -> float via exponent-bias trick: 0x4B0000vv = 8388608 + vv
    return __int_as_float(__byte_perm(packed, 0x4B000000, sel)) - 8388608.0f;
}

__global__ void __launch_bounds__(256) k_apply(float4* __restrict__ out)
{
    __shared__ unsigned int slut[8 * BINS];   // 8 KB

    int blk  = blockIdx.x;          // 0..2047
    int bc   = blk >> 7;            // image
    int seg  = blk & 127;           // 8-row segment
    int band = seg >> 3;            // 64-row band (0..15)
    int i0   = (band == 0) ? 0 : ((band - 1) >> 1);
    int i1   = min(i0 + 1, 7);

    const unsigned char* lb = g_lut8 + ((size_t)bc << 6) * BINS;
#pragma unroll
    for (int s = threadIdx.x; s < 8 * BINS; s += 256) {
        int j0 = s >> 8, b = s & 255;
        int j1 = min(j0 + 1, 7);
        unsigned int v00 = lb[(((i0 << 3) + j0) << 8) + b];
        unsigned int v10 = lb[(((i1 << 3) + j0) << 8) + b];
        unsigned int v01 = lb[(((i0 << 3) + j1) << 8) + b];
        unsigned int v11 = lb[(((i1 << 3) + j1) << 8) + b];
        slut[s] = v00 | (v10 << 8) | (v01 << 16) | (v11 << 24);
    }
    __syncthreads();

    int tid = threadIdx.x;          // == col4 (float4 column), each it = 1 row

    // per-thread loop-invariant x-interpolation setup (4 pixels)
    float wx[4];
    int   jb[4];                    // (j0 << 8), ready to add bin
#pragma unroll
    for (int p = 0; p < 4; p++) {
        int   col = (tid << 2) + p;
        float gj  = fminf(fmaxf((col + 0.5f) * (1.0f / 128.0f) - 0.5f, 0.0f), 7.0f);
        int   j0  = (int)gj;
        wx[p] = gj - (float)j0;
        jb[p] = j0 << 8;
    }

    int row_base = seg << 3;                                // first row (8 rows)
    int f4_base  = (bc << 18) + (row_base << 8) + tid;      // float4 index
    const uchar4* bp = (const uchar4*)g_bidx;

#pragma unroll
    for (int it = 0; it < 8; it++) {
        int   row = row_base + it;
        float gi  = fminf(fmaxf((row + 0.5f) * (1.0f / 128.0f) - 0.5f, 0.0f), 7.0f);
        float wy  = gi - (float)i0;

        int g = f4_base + (it << 8);
        uchar4 b4 = bp[g];
        unsigned int bs[4] = { b4.x, b4.y, b4.z, b4.w };

        float r[4];
#pragma unroll
        for (int p = 0; p < 4; p++) {
            unsigned int packed = slut[jb[p] + bs[p]];
            float v00 = u8f(packed, 0x7440);
            float v10 = u8f(packed, 0x7441);
            float v01 = u8f(packed, 0x7442);
            float v11 = u8f(packed, 0x7443);
            float top = fmaf(wx[p], v01 - v00, v00);
            float bot = fmaf(wx[p], v11 - v10, v10);
            r[p] = fmaf(wy, bot - top, top) * (1.0f / 255.0f);
        }
        __stcs(&out[g], make_float4(r[0], r[1], r[2], r[3]));
    }
}

// ---------------------------------------------------------------------------
// Tail: y is int32; numeric float32 conversion into output tail.
// ---------------------------------------------------------------------------
__global__ void k_tail(const int* __restrict__ y, float* __restrict__ dst, int n)
{
    int i = threadIdx.x;
    if (i < n) dst[i] = (float)y[i];
}

extern "C" void kernel_launch(void* const* d_in, const int* in_sizes, int n_in,
                              void* d_out, int out_size)
{
    const float* x   = (const float*)d_in[0];
    float*       out = (float*)d_out;

    k_reduce  <<<RED_B, 256>>>((const float4*)x);
    k_finalize<<<1, 1024>>>();
    k_hist    <<<TILES, 512>>>(x);
    k_apply   <<<2048, 256>>>((float4*)out);

    int tail = out_size - N_PIX;
    if (tail > 0 && n_in >= 2) {
        k_tail<<<1, 128>>>((const int*)d_in[1], out + N_PIX, tail);
    }
}

// round 7
// speedup vs baseline: 1.0057x; 1.0057x over previous
#include <cuda_runtime.h>
#include <cstdint>
#include <cfloat>

// Problem constants
#define N_PIX   16777216          // 16 * 1 * 1024 * 1024
#define NF4     4194304           // N_PIX / 4
#define RED_B   2048              // reduction blocks
#define BINS    256
#define TILES   1024              // 16 images * 8 * 8
#define CLIPV   2560.0f           // max(int(40.0*16384//256),1)

// Scratch (device globals only — no allocations allowed)
__device__ float         g_pmin[RED_B];
__device__ float         g_pmax[RED_B];
__device__ double        g_psum[RED_B];
__device__ double        g_psq [RED_B];
__device__ float         g_AB[2];
__device__ unsigned int  g_ctr = 0;
__device__ unsigned char g_lut8[TILES * BINS];   // LUT values are exact ints 0..255

// ---------------------------------------------------------------------------
// Kernel 1: partial min/max/sum/sumsq (2048 blocks x 256 thr, 32 elems/thr),
// then the LAST block (threadfence + ticket) reduces the 2048 partials,
// computes the affine constants A,B (fp64 replica of the reference's
// normalize -> standardize -> normalize chain), and writes the y tail.
// ---------------------------------------------------------------------------
__global__ void __launch_bounds__(256) k_reduce(const float4* __restrict__ x,
                                                const int* __restrict__ y,
                                                float* __restrict__ tail_dst,
                                                int tail_n)
{
    int tid = threadIdx.x;
    int t   = blockIdx.x * 256 + tid;

    float mn =  FLT_MAX, mx = -FLT_MAX;
    float s = 0.0f, q = 0.0f;
#pragma unroll
    for (int i = 0; i < 8; i++) {
        float4 v = x[t + i * (RED_B * 256)];
        mn = fminf(mn, fminf(fminf(v.x, v.y), fminf(v.z, v.w)));
        mx = fmaxf(mx, fmaxf(fmaxf(v.x, v.y), fmaxf(v.z, v.w)));
        s += (v.x + v.y) + (v.z + v.w);
        q += (v.x * v.x + v.y * v.y) + (v.z * v.z + v.w * v.w);
    }

    __shared__ float  smn[256], smx[256];
    __shared__ double ss[256], sq[256];
    smn[tid] = mn; smx[tid] = mx;
    ss[tid] = (double)s; sq[tid] = (double)q;
    __syncthreads();
    for (int o = 128; o > 0; o >>= 1) {
        if (tid < o) {
            smn[tid] = fminf(smn[tid], smn[tid + o]);
            smx[tid] = fmaxf(smx[tid], smx[tid + o]);
            ss[tid] += ss[tid + o];
            sq[tid] += sq[tid + o];
        }
        __syncthreads();
    }
    if (tid == 0) {
        g_pmin[blockIdx.x] = smn[0];
        g_pmax[blockIdx.x] = smx[0];
        g_psum[blockIdx.x] = ss[0];
        g_psq [blockIdx.x] = sq[0];
    }

    // ---- last-block-done: finalize + tail ----
    __shared__ bool is_last;
    __threadfence();
    if (tid == 0) {
        unsigned int ticket = atomicAdd(&g_ctr, 1u);
        is_last = (ticket == RED_B - 1);
    }
    __syncthreads();
    if (!is_last) return;

    // reduce 2048 partials: each thread folds 8
    float  lmn =  FLT_MAX, lmx = -FLT_MAX;
    double ls = 0.0, lq = 0.0;
#pragma unroll
    for (int i = 0; i < 8; i++) {
        int k = tid + i * 256;
        lmn = fminf(lmn, g_pmin[k]);
        lmx = fmaxf(lmx, g_pmax[k]);
        ls += g_psum[k];
        lq += g_psq[k];
    }
    __syncthreads();
    smn[tid] = lmn; smx[tid] = lmx; ss[tid] = ls; sq[tid] = lq;
    __syncthreads();
    for (int o = 128; o > 0; o >>= 1) {
        if (tid < o) {
            smn[tid] = fminf(smn[tid], smn[tid + o]);
            smx[tid] = fmaxf(smx[tid], smx[tid + o]);
            ss[tid] += ss[tid + o];
            sq[tid] += sq[tid + o];
        }
        __syncthreads();
    }
    if (tid == 0) {
        double mn2 = (double)smn[0];
        double mx2 = (double)smx[0];
        double span = mx2 - mn2;
        const double N = (double)N_PIX;
        double S = ss[0], Q = sq[0];
        double meanx = S / N;
        double varx  = (Q - S * S / N) / (N - 1.0);
        double mean1 = (meanx - mn2) / span;
        double std1  = sqrt(varx) / span;
        double zmin  = (0.0 - mean1) / std1;
        double zmax  = (1.0 - mean1) / std1;
        double zspan = zmax - zmin;
        double A = 1.0 / (span * std1 * zspan);
        double B = (((0.0 - mn2) / span - mean1) / std1 - zmin) / zspan;
        g_AB[0] = (float)A;
        g_AB[1] = (float)B;
        g_ctr = 0;                 // reset for next graph replay
    }
    // y tail: numeric float32 conversion (y is int32)
    if (tid < tail_n) tail_dst[tid] = (float)y[tid];
}

// ---------------------------------------------------------------------------
// Kernel 2: one 256-thread block per 128x128 tile. 8 warp-private
// sub-histograms (NO bidx store), then clip -> scan -> residual -> LUT.
// x is L2-resident after k_reduce streamed it.
// ---------------------------------------------------------------------------
__global__ void __launch_bounds__(256) k_hist(const float* __restrict__ x)
{
    __shared__ unsigned int h[8][BINS];
    __shared__ float        cs[BINS];

    int t   = blockIdx.x;          // tile id: ((bc*8)+ti)*8+tj
    int tid = threadIdx.x;
#pragma unroll
    for (int k = 0; k < 8; k++) h[k][tid] = 0;
    __syncthreads();

    float A = g_AB[0], B = g_AB[1];

    int bc = t >> 6;
    int ti = (t >> 3) & 7;
    int tj = t & 7;
    int row0 = ti * 128;
    int col0 = tj * 128;
    int wsub = tid >> 5;           // warp-private sub-histogram

    const float4* xp = (const float4*)(x + ((size_t)bc << 20));

#pragma unroll
    for (int it = 0; it < 16; it++) {
        int row   = row0 + it * 8 + (tid >> 5);
        int cidx4 = (row << 8) + (col0 >> 2) + (tid & 31);  // float4 index
        float4 v  = xp[cidx4];
        int b0 = min(max((int)(fmaf(v.x, A, B) * 256.0f), 0), 255);
        int b1 = min(max((int)(fmaf(v.y, A, B) * 256.0f), 0), 255);
        int b2 = min(max((int)(fmaf(v.z, A, B) * 256.0f), 0), 255);
        int b3 = min(max((int)(fmaf(v.w, A, B) * 256.0f), 0), 255);
        atomicAdd(&h[wsub][b0], 1u);
        atomicAdd(&h[wsub][b1], 1u);
        atomicAdd(&h[wsub][b2], 1u);
        atomicAdd(&h[wsub][b3], 1u);
    }
    __syncthreads();

    unsigned int hv = 0;
#pragma unroll
    for (int k = 0; k < 8; k++) hv += h[k][tid];

    // clip + inclusive scan (Hillis-Steele) over 256 bins
    float v = fminf((float)hv, CLIPV);
    cs[tid] = v;
    __syncthreads();
#pragma unroll
    for (int off = 1; off < BINS; off <<= 1) {
        float add = (tid >= off) ? cs[tid - off] : 0.0f;
        __syncthreads();
        cs[tid] += add;
        __syncthreads();
    }
    float total = cs[BINS - 1];
    float resid = (16384.0f - total) * (1.0f / 256.0f);
    float lv = (cs[tid] + (float)(tid + 1) * resid) * (255.0f / 16384.0f);
    lv = floorf(fminf(fmaxf(lv, 0.0f), 255.0f));
    g_lut8[t * BINS + tid] = (unsigned char)lv;
}

// ---------------------------------------------------------------------------
// Kernel 3: bilinear LUT apply — recomputes the bin from x (byte-identical
// expression to k_hist; x is L2-resident) and does ONE LDS.32 per pixel.
// Grid 2048 blocks (image, 8-row segment) x 256 threads.
// slut[(j0,bin)] packs uchar4(v00, v10, v01, v11), j1=min(j0+1,7) folded in.
// ---------------------------------------------------------------------------
__device__ __forceinline__ float u8f(unsigned int packed, int sel)
{
    // byte -> float via exponent-bias trick: 0x4B0000vv = 8388608 + vv
    return __int_as_float(__byte_perm(packed, 0x4B000000, sel)) - 8388608.0f;
}

__global__ void __launch_bounds__(256) k_apply(const float4* __restrict__ x,
                                               float4* __restrict__ out)
{
    __shared__ unsigned int slut[8 * BINS];   // 8 KB

    int blk  = blockIdx.x;          // 0..2047
    int bc   = blk >> 7;            // image
    int seg  = blk & 127;           // 8-row segment
    int band = seg >> 3;            // 64-row band (0..15)
    int i0   = (band == 0) ? 0 : ((band - 1) >> 1);
    int i1   = min(i0 + 1, 7);

    const unsigned char* lb = g_lut8 + ((size_t)bc << 6) * BINS;
#pragma unroll
    for (int s = threadIdx.x; s < 8 * BINS; s += 256) {
        int j0 = s >> 8, b = s & 255;
        int j1 = min(j0 + 1, 7);
        unsigned int v00 = lb[(((i0 << 3) + j0) << 8) + b];
        unsigned int v10 = lb[(((i1 << 3) + j0) << 8) + b];
        unsigned int v01 = lb[(((i0 << 3) + j1) << 8) + b];
        unsigned int v11 = lb[(((i1 << 3) + j1) << 8) + b];
        slut[s] = v00 | (v10 << 8) | (v01 << 16) | (v11 << 24);
    }
    __syncthreads();

    float A = g_AB[0], B = g_AB[1];
    int tid = threadIdx.x;          // == col4 (float4 column), each it = 1 row

    // per-thread loop-invariant x-interpolation setup (4 pixels)
    float wx[4];
    int   jb[4];                    // (j0 << 8), ready to add bin
#pragma unroll
    for (int p = 0; p < 4; p++) {
        int   col = (tid << 2) + p;
        float gj  = fminf(fmaxf((col + 0.5f) * (1.0f / 128.0f) - 0.5f, 0.0f), 7.0f);
        int   j0  = (int)gj;
        wx[p] = gj - (float)j0;
        jb[p] = j0 << 8;
    }

    int row_base = seg << 3;                                // first row (8 rows)
    int f4_base  = (bc << 18) + (row_base << 8) + tid;      // float4 index

#pragma unroll
    for (int it = 0; it < 8; it++) {
        int   row = row_base + it;
        float gi  = fminf(fmaxf((row + 0.5f) * (1.0f / 128.0f) - 0.5f, 0.0f), 7.0f);
        float wy  = gi - (float)i0;

        int g = f4_base + (it << 8);
        float4 v = x[g];
        int bs[4];
        bs[0] = min(max((int)(fmaf(v.x, A, B) * 256.0f), 0), 255);
        bs[1] = min(max((int)(fmaf(v.y, A, B) * 256.0f), 0), 255);
        bs[2] = min(max((int)(fmaf(v.z, A, B) * 256.0f), 0), 255);
        bs[3] = min(max((int)(fmaf(v.w, A, B) * 256.0f), 0), 255);

        float r[4];
#pragma unroll
        for (int p = 0; p < 4; p++) {
            unsigned int packed = slut[jb[p] + bs[p]];
            float v00 = u8f(packed, 0x7440);
            float v10 = u8f(packed, 0x7441);
            float v01 = u8f(packed, 0x7442);
            float v11 = u8f(packed, 0x7443);
            float top = fmaf(wx[p], v01 - v00, v00);
            float bot = fmaf(wx[p], v11 - v10, v10);
            r[p] = fmaf(wy, bot - top, top) * (1.0f / 255.0f);
        }
        __stcs(&out[g], make_float4(r[0], r[1], r[2], r[3]));
    }
}

extern "C" void kernel_launch(void* const* d_in, const int* in_sizes, int n_in,
                              void* d_out, int out_size)
{
    const float* x   = (const float*)d_in[0];
    const int*   y   = (n_in >= 2) ? (const int*)d_in[1] : nullptr;
    float*       out = (float*)d_out;

    int tail = out_size - N_PIX;
    if (tail < 0) tail = 0;

    k_reduce<<<RED_B, 256>>>((const float4*)x, y, out + N_PIX, tail);
    k_hist  <<<TILES, 256>>>(x);
    k_apply <<<2048, 256>>>((const float4*)x, (float4*)out);
}

// round 8
// speedup vs baseline: 1.0352x; 1.0293x over previous
#include <cuda_runtime.h>
#include <cstdint>
#include <cfloat>

// Problem constants
#define N_PIX   16777216          // 16 * 1 * 1024 * 1024
#define NF4     4194304           // N_PIX / 4
#define RED_B   2048              // reduction blocks
#define BINS    256
#define TILES   1024              // 16 images * 8 * 8
#define CLIPV   2560.0f           // max(int(40.0*16384//256),1)

// Scratch (device globals only — no allocations allowed)
__device__ float         g_pmin[RED_B];
__device__ float         g_pmax[RED_B];
__device__ double        g_psum[RED_B];
__device__ double        g_psq [RED_B];
__device__ float         g_AB[2];
__device__ unsigned int  g_ctr = 0;
__device__ unsigned char g_lut8[TILES * BINS];   // LUT values are exact ints 0..255

// ---------------------------------------------------------------------------
// Kernel 1: partial min/max/sum/sumsq (2048 blocks x 256 thr, 32 elems/thr),
// loads FRONT-BATCHED into registers (8 independent LDG.128 in flight -> MLP 8)
// before any consumption. Last block (threadfence + ticket) reduces the 2048
// partials, computes affine constants A,B, and writes the y tail.
// ---------------------------------------------------------------------------
__global__ void __launch_bounds__(256) k_reduce(const float4* __restrict__ x,
                                                const int* __restrict__ y,
                                                float* __restrict__ tail_dst,
                                                int tail_n)
{
    int tid = threadIdx.x;
    int t   = blockIdx.x * 256 + tid;

    // ---- phase 1: issue all 8 loads with no consumers between them ----
    float4 vs[8];
#pragma unroll
    for (int i = 0; i < 8; i++)
        vs[i] = x[t + i * (RED_B * 256)];

    // ---- phase 2: reduce ----
    float mn =  FLT_MAX, mx = -FLT_MAX;
    float s = 0.0f, q = 0.0f;
#pragma unroll
    for (int i = 0; i < 8; i++) {
        float4 v = vs[i];
        mn = fminf(mn, fminf(fminf(v.x, v.y), fminf(v.z, v.w)));
        mx = fmaxf(mx, fmaxf(fmaxf(v.x, v.y), fmaxf(v.z, v.w)));
        s += (v.x + v.y) + (v.z + v.w);
        q += (v.x * v.x + v.y * v.y) + (v.z * v.z + v.w * v.w);
    }

    __shared__ float  smn[256], smx[256];
    __shared__ double ss[256], sq[256];
    smn[tid] = mn; smx[tid] = mx;
    ss[tid] = (double)s; sq[tid] = (double)q;
    __syncthreads();
    for (int o = 128; o > 0; o >>= 1) {
        if (tid < o) {
            smn[tid] = fminf(smn[tid], smn[tid + o]);
            smx[tid] = fmaxf(smx[tid], smx[tid + o]);
            ss[tid] += ss[tid + o];
            sq[tid] += sq[tid + o];
        }
        __syncthreads();
    }
    if (tid == 0) {
        g_pmin[blockIdx.x] = smn[0];
        g_pmax[blockIdx.x] = smx[0];
        g_psum[blockIdx.x] = ss[0];
        g_psq [blockIdx.x] = sq[0];
    }

    // ---- last-block-done: finalize + tail ----
    __shared__ bool is_last;
    __threadfence();
    if (tid == 0) {
        unsigned int ticket = atomicAdd(&g_ctr, 1u);
        is_last = (ticket == RED_B - 1);
    }
    __syncthreads();
    if (!is_last) return;

    // reduce 2048 partials: each thread folds 8
    float  lmn =  FLT_MAX, lmx = -FLT_MAX;
    double ls = 0.0, lq = 0.0;
#pragma unroll
    for (int i = 0; i < 8; i++) {
        int k = tid + i * 256;
        lmn = fminf(lmn, g_pmin[k]);
        lmx = fmaxf(lmx, g_pmax[k]);
        ls += g_psum[k];
        lq += g_psq[k];
    }
    __syncthreads();
    smn[tid] = lmn; smx[tid] = lmx; ss[tid] = ls; sq[tid] = lq;
    __syncthreads();
    for (int o = 128; o > 0; o >>= 1) {
        if (tid < o) {
            smn[tid] = fminf(smn[tid], smn[tid + o]);
            smx[tid] = fmaxf(smx[tid], smx[tid + o]);
            ss[tid] += ss[tid + o];
            sq[tid] += sq[tid + o];
        }
        __syncthreads();
    }
    if (tid == 0) {
        double mn2 = (double)smn[0];
        double mx2 = (double)smx[0];
        double span = mx2 - mn2;
        const double N = (double)N_PIX;
        double S = ss[0], Q = sq[0];
        double meanx = S / N;
        double varx  = (Q - S * S / N) / (N - 1.0);
        double mean1 = (meanx - mn2) / span;
        double std1  = sqrt(varx) / span;
        double zmin  = (0.0 - mean1) / std1;
        double zmax  = (1.0 - mean1) / std1;
        double zspan = zmax - zmin;
        double A = 1.0 / (span * std1 * zspan);
        double B = (((0.0 - mn2) / span - mean1) / std1 - zmin) / zspan;
        g_AB[0] = (float)A;
        g_AB[1] = (float)B;
        g_ctr = 0;                 // reset for next graph replay
    }
    // y tail: numeric float32 conversion (y is int32)
    if (tid < tail_n) tail_dst[tid] = (float)y[tid];
}

// ---------------------------------------------------------------------------
// Kernel 2: one 256-thread block per 128x128 tile. 8 warp-private
// sub-histograms (no bidx store), then clip -> scan -> residual -> LUT.
// x is L2-resident after k_reduce streamed it.
// ---------------------------------------------------------------------------
__global__ void __launch_bounds__(256) k_hist(const float* __restrict__ x)
{
    __shared__ unsigned int h[8][BINS];
    __shared__ float        cs[BINS];

    int t   = blockIdx.x;          // tile id: ((bc*8)+ti)*8+tj
    int tid = threadIdx.x;
#pragma unroll
    for (int k = 0; k < 8; k++) h[k][tid] = 0;
    __syncthreads();

    float A = g_AB[0], B = g_AB[1];

    int bc = t >> 6;
    int ti = (t >> 3) & 7;
    int tj = t & 7;
    int row0 = ti * 128;
    int col0 = tj * 128;
    int wsub = tid >> 5;           // warp-private sub-histogram

    const float4* xp = (const float4*)(x + ((size_t)bc << 20));

#pragma unroll
    for (int it = 0; it < 16; it++) {
        int row   = row0 + it * 8 + (tid >> 5);
        int cidx4 = (row << 8) + (col0 >> 2) + (tid & 31);  // float4 index
        float4 v  = xp[cidx4];
        int b0 = min(max((int)(fmaf(v.x, A, B) * 256.0f), 0), 255);
        int b1 = min(max((int)(fmaf(v.y, A, B) * 256.0f), 0), 255);
        int b2 = min(max((int)(fmaf(v.z, A, B) * 256.0f), 0), 255);
        int b3 = min(max((int)(fmaf(v.w, A, B) * 256.0f), 0), 255);
        atomicAdd(&h[wsub][b0], 1u);
        atomicAdd(&h[wsub][b1], 1u);
        atomicAdd(&h[wsub][b2], 1u);
        atomicAdd(&h[wsub][b3], 1u);
    }
    __syncthreads();

    unsigned int hv = 0;
#pragma unroll
    for (int k = 0; k < 8; k++) hv += h[k][tid];

    // clip + inclusive scan (Hillis-Steele) over 256 bins
    float v = fminf((float)hv, CLIPV);
    cs[tid] = v;
    __syncthreads();
#pragma unroll
    for (int off = 1; off < BINS; off <<= 1) {
        float add = (tid >= off) ? cs[tid - off] : 0.0f;
        __syncthreads();
        cs[tid] += add;
        __syncthreads();
    }
    float total = cs[BINS - 1];
    float resid = (16384.0f - total) * (1.0f / 256.0f);
    float lv = (cs[tid] + (float)(tid + 1) * resid) * (255.0f / 16384.0f);
    lv = floorf(fminf(fmaxf(lv, 0.0f), 255.0f));
    g_lut8[t * BINS + tid] = (unsigned char)lv;
}

// ---------------------------------------------------------------------------
// Kernel 3: bilinear LUT apply — recomputes the bin from x (byte-identical
// expression to k_hist; x is L2-resident), ONE LDS.32 per pixel, and the x[g]
// load software-pipelined one iteration ahead.
// ---------------------------------------------------------------------------
__device__ __forceinline__ float u8f(unsigned int packed, int sel)
{
    // byte -> float via exponent-bias trick: 0x4B0000vv = 8388608 + vv
    return __int_as_float(__byte_perm(packed, 0x4B000000, sel)) - 8388608.0f;
}

__global__ void __launch_bounds__(256) k_apply(const float4* __restrict__ x,
                                               float4* __restrict__ out)
{
    __shared__ unsigned int slut[8 * BINS];   // 8 KB

    int blk  = blockIdx.x;          // 0..2047
    int bc   = blk >> 7;            // image
    int seg  = blk & 127;           // 8-row segment
    int band = seg >> 3;            // 64-row band (0..15)
    int i0   = (band == 0) ? 0 : ((band - 1) >> 1);
    int i1   = min(i0 + 1, 7);

    const unsigned char* lb = g_lut8 + ((size_t)bc << 6) * BINS;
#pragma unroll
    for (int s = threadIdx.x; s < 8 * BINS; s += 256) {
        int j0 = s >> 8, b = s & 255;
        int j1 = min(j0 + 1, 7);
        unsigned int v00 = lb[(((i0 << 3) + j0) << 8) + b];
        unsigned int v10 = lb[(((i1 << 3) + j0) << 8) + b];
        unsigned int v01 = lb[(((i0 << 3) + j1) << 8) + b];
        unsigned int v11 = lb[(((i1 << 3) + j1) << 8) + b];
        slut[s] = v00 | (v10 << 8) | (v01 << 16) | (v11 << 24);
    }
    __syncthreads();

    float A = g_AB[0], B = g_AB[1];
    int tid = threadIdx.x;          // == col4 (float4 column), each it = 1 row

    // per-thread loop-invariant x-interpolation setup (4 pixels)
    float wx[4];
    int   jb[4];                    // (j0 << 8), ready to add bin
#pragma unroll
    for (int p = 0; p < 4; p++) {
        int   col = (tid << 2) + p;
        float gj  = fminf(fmaxf((col + 0.5f) * (1.0f / 128.0f) - 0.5f, 0.0f), 7.0f);
        int   j0  = (int)gj;
        wx[p] = gj - (float)j0;
        jb[p] = j0 << 8;
    }

    int row_base = seg << 3;                                // first row (8 rows)
    int f4_base  = (bc << 18) + (row_base << 8) + tid;      // float4 index

    float4 v = x[f4_base];                                  // prologue load
#pragma unroll
    for (int it = 0; it < 8; it++) {
        float4 vn;
        if (it < 7) vn = x[f4_base + ((it + 1) << 8)];      // prefetch next row

        int   row = row_base + it;
        float gi  = fminf(fmaxf((row + 0.5f) * (1.0f / 128.0f) - 0.5f, 0.0f), 7.0f);
        float wy  = gi - (float)i0;

        int bs[4];
        bs[0] = min(max((int)(fmaf(v.x, A, B) * 256.0f), 0), 255);
        bs[1] = min(max((int)(fmaf(v.y, A, B) * 256.0f), 0), 255);
        bs[2] = min(max((int)(fmaf(v.z, A, B) * 256.0f), 0), 255);
        bs[3] = min(max((int)(fmaf(v.w, A, B) * 256.0f), 0), 255);

        float r[4];
#pragma unroll
        for (int p = 0; p < 4; p++) {
            unsigned int packed = slut[jb[p] + bs[p]];
            float v00 = u8f(packed, 0x7440);
            float v10 = u8f(packed, 0x7441);
            float v01 = u8f(packed, 0x7442);
            float v11 = u8f(packed, 0x7443);
            float top = fmaf(wx[p], v01 - v00, v00);
            float bot = fmaf(wx[p], v11 - v10, v10);
            r[p] = fmaf(wy, bot - top, top) * (1.0f / 255.0f);
        }
        __stcs(&out[f4_base + (it << 8)], make_float4(r[0], r[1], r[2], r[3]));
        v = vn;
    }
}

extern "C" void kernel_launch(void* const* d_in, const int* in_sizes, int n_in,
                              void* d_out, int out_size)
{
    const float* x   = (const float*)d_in[0];
    const int*   y   = (n_in >= 2) ? (const int*)d_in[1] : nullptr;
    float*       out = (float*)d_out;

    int tail = out_size - N_PIX;
    if (tail < 0) tail = 0;

    k_reduce<<<RED_B, 256>>>((const float4*)x, y, out + N_PIX, tail);
    k_hist  <<<TILES, 256>>>(x);
    k_apply <<<2048, 256>>>((const float4*)x, (float4*)out);
}

// round 9
// speedup vs baseline: 1.0436x; 1.0081x over previous
#include <cuda_runtime.h>
#include <cstdint>
#include <cfloat>

// Problem constants
#define N_PIX   16777216          // 16 * 1 * 1024 * 1024
#define NF4     4194304           // N_PIX / 4
#define RED_B   2048              // reduction blocks
#define BINS    256
#define TILES   1024              // 16 images * 8 * 8
#define CLIPV   2560.0f           // max(int(40.0*16384//256),1)

// Scratch (device globals only — no allocations allowed)
__device__ float         g_pmin[RED_B];
__device__ float         g_pmax[RED_B];
__device__ double        g_psum[RED_B];
__device__ double        g_psq [RED_B];
__device__ float         g_AB[2];
__device__ unsigned int  g_ctr = 0;
__device__ unsigned char g_lut8[TILES * BINS];   // LUT values are exact ints 0..255

// ---------------------------------------------------------------------------
// Kernel 1: partial min/max/sum/sumsq (2048 blocks x 256 thr, 32 elems/thr).
// The 8 LDG.128 are issued via asm volatile so ptxas CANNOT sink them to the
// consumers: all 8 are in flight simultaneously (MLP=8). Last block
// (threadfence + ticket) reduces the 2048 partials, computes affine constants
// A,B (fp64 replica of the reference chain), and writes the y tail.
// ---------------------------------------------------------------------------
__global__ void __launch_bounds__(256) k_reduce(const float4* __restrict__ x,
                                                const int* __restrict__ y,
                                                float* __restrict__ tail_dst,
                                                int tail_n)
{
    int tid = threadIdx.x;
    int t   = blockIdx.x * 256 + tid;

    // ---- phase 1: 8 independent loads, pinned in program order ----
    float4 vs[8];
#pragma unroll
    for (int i = 0; i < 8; i++) {
        const float4* p = x + t + i * (RED_B * 256);
        asm volatile("ld.global.nc.v4.f32 {%0,%1,%2,%3}, [%4];"
                     : "=f"(vs[i].x), "=f"(vs[i].y), "=f"(vs[i].z), "=f"(vs[i].w)
                     : "l"(p));
    }

    // ---- phase 2: reduce ----
    float mn =  FLT_MAX, mx = -FLT_MAX;
    float s = 0.0f, q = 0.0f;
#pragma unroll
    for (int i = 0; i < 8; i++) {
        float4 v = vs[i];
        mn = fminf(mn, fminf(fminf(v.x, v.y), fminf(v.z, v.w)));
        mx = fmaxf(mx, fmaxf(fmaxf(v.x, v.y), fmaxf(v.z, v.w)));
        s += (v.x + v.y) + (v.z + v.w);
        q += (v.x * v.x + v.y * v.y) + (v.z * v.z + v.w * v.w);
    }

    __shared__ float  smn[256], smx[256];
    __shared__ double ss[256], sq[256];
    smn[tid] = mn; smx[tid] = mx;
    ss[tid] = (double)s; sq[tid] = (double)q;
    __syncthreads();
    for (int o = 128; o > 0; o >>= 1) {
        if (tid < o) {
            smn[tid] = fminf(smn[tid], smn[tid + o]);
            smx[tid] = fmaxf(smx[tid], smx[tid + o]);
            ss[tid] += ss[tid + o];
            sq[tid] += sq[tid + o];
        }
        __syncthreads();
    }
    if (tid == 0) {
        g_pmin[blockIdx.x] = smn[0];
        g_pmax[blockIdx.x] = smx[0];
        g_psum[blockIdx.x] = ss[0];
        g_psq [blockIdx.x] = sq[0];
    }

    // ---- last-block-done: finalize + tail ----
    __shared__ bool is_last;
    __threadfence();
    if (tid == 0) {
        unsigned int ticket = atomicAdd(&g_ctr, 1u);
        is_last = (ticket == RED_B - 1);
    }
    __syncthreads();
    if (!is_last) return;

    // reduce 2048 partials: each thread folds 8
    float  lmn =  FLT_MAX, lmx = -FLT_MAX;
    double ls = 0.0, lq = 0.0;
#pragma unroll
    for (int i = 0; i < 8; i++) {
        int k = tid + i * 256;
        lmn = fminf(lmn, g_pmin[k]);
        lmx = fmaxf(lmx, g_pmax[k]);
        ls += g_psum[k];
        lq += g_psq[k];
    }
    __syncthreads();
    smn[tid] = lmn; smx[tid] = lmx; ss[tid] = ls; sq[tid] = lq;
    __syncthreads();
    for (int o = 128; o > 0; o >>= 1) {
        if (tid < o) {
            smn[tid] = fminf(smn[tid], smn[tid + o]);
            smx[tid] = fmaxf(smx[tid], smx[tid + o]);
            ss[tid] += ss[tid + o];
            sq[tid] += sq[tid + o];
        }
        __syncthreads();
    }
    if (tid == 0) {
        double mn2 = (double)smn[0];
        double mx2 = (double)smx[0];
        double span = mx2 - mn2;
        const double N = (double)N_PIX;
        double S = ss[0], Q = sq[0];
        double meanx = S / N;
        double varx  = (Q - S * S / N) / (N - 1.0);
        double mean1 = (meanx - mn2) / span;
        double std1  = sqrt(varx) / span;
        double zmin  = (0.0 - mean1) / std1;
        double zmax  = (1.0 - mean1) / std1;
        double zspan = zmax - zmin;
        double A = 1.0 / (span * std1 * zspan);
        double B = (((0.0 - mn2) / span - mean1) / std1 - zmin) / zspan;
        g_AB[0] = (float)A;
        g_AB[1] = (float)B;
        g_ctr = 0;                 // reset for next graph replay
    }
    // y tail: numeric float32 conversion (y is int32)
    if (tid < tail_n) tail_dst[tid] = (float)y[tid];
}

// ---------------------------------------------------------------------------
// Kernel 2: one 256-thread block per 128x128 tile. 8 warp-private
// sub-histograms (no bidx store), then clip -> scan -> residual -> LUT.
// x is L2-resident after k_reduce streamed it.
// ---------------------------------------------------------------------------
__global__ void __launch_bounds__(256) k_hist(const float* __restrict__ x)
{
    __shared__ unsigned int h[8][BINS];
    __shared__ float        cs[BINS];

    int t   = blockIdx.x;          // tile id: ((bc*8)+ti)*8+tj
    int tid = threadIdx.x;
#pragma unroll
    for (int k = 0; k < 8; k++) h[k][tid] = 0;
    __syncthreads();

    float A = g_AB[0], B = g_AB[1];

    int bc = t >> 6;
    int ti = (t >> 3) & 7;
    int tj = t & 7;
    int row0 = ti * 128;
    int col0 = tj * 128;
    int wsub = tid >> 5;           // warp-private sub-histogram

    const float4* xp = (const float4*)(x + ((size_t)bc << 20));

#pragma unroll
    for (int it = 0; it < 16; it++) {
        int row   = row0 + it * 8 + (tid >> 5);
        int cidx4 = (row << 8) + (col0 >> 2) + (tid & 31);  // float4 index
        float4 v  = xp[cidx4];
        int b0 = min(max((int)(fmaf(v.x, A, B) * 256.0f), 0), 255);
        int b1 = min(max((int)(fmaf(v.y, A, B) * 256.0f), 0), 255);
        int b2 = min(max((int)(fmaf(v.z, A, B) * 256.0f), 0), 255);
        int b3 = min(max((int)(fmaf(v.w, A, B) * 256.0f), 0), 255);
        atomicAdd(&h[wsub][b0], 1u);
        atomicAdd(&h[wsub][b1], 1u);
        atomicAdd(&h[wsub][b2], 1u);
        atomicAdd(&h[wsub][b3], 1u);
    }
    __syncthreads();

    unsigned int hv = 0;
#pragma unroll
    for (int k = 0; k < 8; k++) hv += h[k][tid];

    // clip + inclusive scan (Hillis-Steele) over 256 bins
    float v = fminf((float)hv, CLIPV);
    cs[tid] = v;
    __syncthreads();
#pragma unroll
    for (int off = 1; off < BINS; off <<= 1) {
        float add = (tid >= off) ? cs[tid - off] : 0.0f;
        __syncthreads();
        cs[tid] += add;
        __syncthreads();
    }
    float total = cs[BINS - 1];
    float resid = (16384.0f - total) * (1.0f / 256.0f);
    float lv = (cs[tid] + (float)(tid + 1) * resid) * (255.0f / 16384.0f);
    lv = floorf(fminf(fmaxf(lv, 0.0f), 255.0f));
    g_lut8[t * BINS + tid] = (unsigned char)lv;
}

// ---------------------------------------------------------------------------
// Kernel 3: bilinear LUT apply — recomputes the bin from x (byte-identical
// expression to k_hist; x is L2-resident), ONE LDS.32 per pixel, x[g] load
// software-pipelined one iteration ahead.
// ---------------------------------------------------------------------------
__device__ __forceinline__ float u8f(unsigned int packed, int sel)
{
    // byte -> float via exponent-bias trick: 0x4B0000vv = 8388608 + vv
    return __int_as_float(__byte_perm(packed, 0x4B000000, sel)) - 8388608.0f;
}

__global__ void __launch_bounds__(256) k_apply(const float4* __restrict__ x,
                                               float4* __restrict__ out)
{
    __shared__ unsigned int slut[8 * BINS];   // 8 KB

    int blk  = blockIdx.x;          // 0..2047
    int bc   = blk >> 7;            // image
    int seg  = blk & 127;           // 8-row segment
    int band = seg >> 3;            // 64-row band (0..15)
    int i0   = (band == 0) ? 0 : ((band - 1) >> 1);
    int i1   = min(i0 + 1, 7);

    const unsigned char* lb = g_lut8 + ((size_t)bc << 6) * BINS;
#pragma unroll
    for (int s = threadIdx.x; s < 8 * BINS; s += 256) {
        int j0 = s >> 8, b = s & 255;
        int j1 = min(j0 + 1, 7);
        unsigned int v00 = lb[(((i0 << 3) + j0) << 8) + b];
        unsigned int v10 = lb[(((i1 << 3) + j0) << 8) + b];
        unsigned int v01 = lb[(((i0 << 3) + j1) << 8) + b];
        unsigned int v11 = lb[(((i1 << 3) + j1) << 8) + b];
        slut[s] = v00 | (v10 << 8) | (v01 << 16) | (v11 << 24);
    }
    __syncthreads();

    float A = g_AB[0], B = g_AB[1];
    int tid = threadIdx.x;          // == col4 (float4 column), each it = 1 row

    // per-thread loop-invariant x-interpolation setup (4 pixels)
    float wx[4];
    int   jb[4];                    // (j0 << 8), ready to add bin
#pragma unroll
    for (int p = 0; p < 4; p++) {
        int   col = (tid << 2) + p;
        float gj  = fminf(fmaxf((col + 0.5f) * (1.0f / 128.0f) - 0.5f, 0.0f), 7.0f);
        int   j0  = (int)gj;
        wx[p] = gj - (float)j0;
        jb[p] = j0 << 8;
    }

    int row_base = seg << 3;                                // first row (8 rows)
    int f4_base  = (bc << 18) + (row_base << 8) + tid;      // float4 index

    float4 v = x[f4_base];                                  // prologue load
#pragma unroll
    for (int it = 0; it < 8; it++) {
        float4 vn;
        if (it < 7) vn = x[f4_base + ((it + 1) << 8)];      // prefetch next row

        int   row = row_base + it;
        float gi  = fminf(fmaxf((row + 0.5f) * (1.0f / 128.0f) - 0.5f, 0.0f), 7.0f);
        float wy  = gi - (float)i0;

        int bs[4];
        bs[0] = min(max((int)(fmaf(v.x, A, B) * 256.0f), 0), 255);
        bs[1] = min(max((int)(fmaf(v.y, A, B) * 256.0f), 0), 255);
        bs[2] = min(max((int)(fmaf(v.z, A, B) * 256.0f), 0), 255);
        bs[3] = min(max((int)(fmaf(v.w, A, B) * 256.0f), 0), 255);

        float r[4];
#pragma unroll
        for (int p = 0; p < 4; p++) {
            unsigned int packed = slut[jb[p] + bs[p]];
            float v00 = u8f(packed, 0x7440);
            float v10 = u8f(packed, 0x7441);
            float v01 = u8f(packed, 0x7442);
            float v11 = u8f(packed, 0x7443);
            float top = fmaf(wx[p], v01 - v00, v00);
            float bot = fmaf(wx[p], v11 - v10, v10);
            r[p] = fmaf(wy, bot - top, top) * (1.0f / 255.0f);
        }
        __stcs(&out[f4_base + (it << 8)], make_float4(r[0], r[1], r[2], r[3]));
        v = vn;
    }
}

extern "C" void kernel_launch(void* const* d_in, const int* in_sizes, int n_in,
                              void* d_out, int out_size)
{
    const float* x   = (const float*)d_in[0];
    const int*   y   = (n_in >= 2) ? (const int*)d_in[1] : nullptr;
    float*       out = (float*)d_out;

    int tail = out_size - N_PIX;
    if (tail < 0) tail = 0;

    k_reduce<<<RED_B, 256>>>((const float4*)x, y, out + N_PIX, tail);
    k_hist  <<<TILES, 256>>>(x);
    k_apply <<<2048, 256>>>((const float4*)x, (float4*)out);
}

// round 10
// speedup vs baseline: 1.0509x; 1.0070x over previous
#include <cuda_runtime.h>
#include <cstdint>
#include <cfloat>

// Problem constants
#define N_PIX   16777216          // 16 * 1 * 1024 * 1024
#define NF4     4194304           // N_PIX / 4
#define RED_B   2048              // reduction blocks
#define BINS    256
#define TILES   1024              // 16 images * 8 * 8
#define CLIPV   2560.0f           // max(int(40.0*16384//256),1)

// Scratch (device globals only — no allocations allowed)
__device__ float         g_pmin[RED_B];
__device__ float         g_pmax[RED_B];
__device__ double        g_psum[RED_B];
__device__ double        g_psq [RED_B];
__device__ float         g_AB[2];
__device__ unsigned int  g_ctr = 0;
__device__ unsigned char g_lut8[TILES * BINS];   // LUT values are exact ints 0..255

__device__ __forceinline__ unsigned int smem_u32(const void* p)
{
    unsigned int a;
    asm("{ .reg .u64 t; cvta.to.shared.u64 t, %1; cvt.u32.u64 %0, t; }"
        : "=r"(a) : "l"(p));
    return a;
}

// ---------------------------------------------------------------------------
// Kernel 1: partial min/max/sum/sumsq (2048 blocks x 256 thr, 32 elems/thr).
// Loads go through cp.async (LDGSTS) into a 32 KB smem staging buffer: no
// destination register -> ptxas CANNOT serialize them -> true MLP=8.
// Layout sbuf[i*256+tid] gives conflict-free LDS.128 readback; each thread
// reads only its own slots, so wait_group 0 suffices (no __syncthreads).
// Last block (threadfence + ticket) reduces the 2048 partials, computes the
// affine constants A,B (fp64 replica of the reference chain), writes y tail.
// ---------------------------------------------------------------------------
__global__ void __launch_bounds__(256) k_reduce(const float4* __restrict__ x,
                                                const int* __restrict__ y,
                                                float* __restrict__ tail_dst,
                                                int tail_n)
{
    __shared__ float4 sbuf[8 * 256];        // 32 KB staging
    __shared__ float  smn[256], smx[256];
    __shared__ double ss[256], sq[256];

    int tid = threadIdx.x;
    int t   = blockIdx.x * 256 + tid;

    // ---- phase 1: 8 async copies, all in flight at once ----
#pragma unroll
    for (int i = 0; i < 8; i++) {
        unsigned int dst = smem_u32(&sbuf[i * 256 + tid]);
        const float4* src = x + t + i * (RED_B * 256);
        asm volatile("cp.async.cg.shared.global [%0], [%1], 16;"
                     :: "r"(dst), "l"(src));
    }
    asm volatile("cp.async.commit_group;");
    asm volatile("cp.async.wait_group 0;" ::: "memory");

    // ---- phase 2: reduce own slots ----
    float mn =  FLT_MAX, mx = -FLT_MAX;
    float s = 0.0f, q = 0.0f;
#pragma unroll
    for (int i = 0; i < 8; i++) {
        float4 v = sbuf[i * 256 + tid];
        mn = fminf(mn, fminf(fminf(v.x, v.y), fminf(v.z, v.w)));
        mx = fmaxf(mx, fmaxf(fmaxf(v.x, v.y), fmaxf(v.z, v.w)));
        s += (v.x + v.y) + (v.z + v.w);
        q += (v.x * v.x + v.y * v.y) + (v.z * v.z + v.w * v.w);
    }

    smn[tid] = mn; smx[tid] = mx;
    ss[tid] = (double)s; sq[tid] = (double)q;
    __syncthreads();
    for (int o = 128; o > 0; o >>= 1) {
        if (tid < o) {
            smn[tid] = fminf(smn[tid], smn[tid + o]);
            smx[tid] = fmaxf(smx[tid], smx[tid + o]);
            ss[tid] += ss[tid + o];
            sq[tid] += sq[tid + o];
        }
        __syncthreads();
    }
    if (tid == 0) {
        g_pmin[blockIdx.x] = smn[0];
        g_pmax[blockIdx.x] = smx[0];
        g_psum[blockIdx.x] = ss[0];
        g_psq [blockIdx.x] = sq[0];
    }

    // ---- last-block-done: finalize + tail ----
    __shared__ bool is_last;
    __threadfence();
    if (tid == 0) {
        unsigned int ticket = atomicAdd(&g_ctr, 1u);
        is_last = (ticket == RED_B - 1);
    }
    __syncthreads();
    if (!is_last) return;

    // reduce 2048 partials: each thread folds 8
    float  lmn =  FLT_MAX, lmx = -FLT_MAX;
    double ls = 0.0, lq = 0.0;
#pragma unroll
    for (int i = 0; i < 8; i++) {
        int k = tid + i * 256;
        lmn = fminf(lmn, g_pmin[k]);
        lmx = fmaxf(lmx, g_pmax[k]);
        ls += g_psum[k];
        lq += g_psq[k];
    }
    __syncthreads();
    smn[tid] = lmn; smx[tid] = lmx; ss[tid] = ls; sq[tid] = lq;
    __syncthreads();
    for (int o = 128; o > 0; o >>= 1) {
        if (tid < o) {
            smn[tid] = fminf(smn[tid], smn[tid + o]);
            smx[tid] = fmaxf(smx[tid], smx[tid + o]);
            ss[tid] += ss[tid + o];
            sq[tid] += sq[tid + o];
        }
        __syncthreads();
    }
    if (tid == 0) {
        double mn2 = (double)smn[0];
        double mx2 = (double)smx[0];
        double span = mx2 - mn2;
        const double N = (double)N_PIX;
        double S = ss[0], Q = sq[0];
        double meanx = S / N;
        double varx  = (Q - S * S / N) / (N - 1.0);
        double mean1 = (meanx - mn2) / span;
        double std1  = sqrt(varx) / span;
        double zmin  = (0.0 - mean1) / std1;
        double zmax  = (1.0 - mean1) / std1;
        double zspan = zmax - zmin;
        double A = 1.0 / (span * std1 * zspan);
        double B = (((0.0 - mn2) / span - mean1) / std1 - zmin) / zspan;
        g_AB[0] = (float)A;
        g_AB[1] = (float)B;
        g_ctr = 0;                 // reset for next graph replay
    }
    // y tail: numeric float32 conversion (y is int32)
    if (tid < tail_n) tail_dst[tid] = (float)y[tid];
}

// ---------------------------------------------------------------------------
// Kernel 2: one 256-thread block per 128x128 tile. 8 warp-private
// sub-histograms (no bidx store), then clip -> scan -> residual -> LUT.
// x is L2-resident after k_reduce streamed it.
// ---------------------------------------------------------------------------
__global__ void __launch_bounds__(256) k_hist(const float* __restrict__ x)
{
    __shared__ unsigned int h[8][BINS];
    __shared__ float        cs[BINS];

    int t   = blockIdx.x;          // tile id: ((bc*8)+ti)*8+tj
    int tid = threadIdx.x;
#pragma unroll
    for (int k = 0; k < 8; k++) h[k][tid] = 0;
    __syncthreads();

    float A = g_AB[0], B = g_AB[1];

    int bc = t >> 6;
    int ti = (t >> 3) & 7;
    int tj = t & 7;
    int row0 = ti * 128;
    int col0 = tj * 128;
    int wsub = tid >> 5;           // warp-private sub-histogram

    const float4* xp = (const float4*)(x + ((size_t)bc << 20));

#pragma unroll
    for (int it = 0; it < 16; it++) {
        int row   = row0 + it * 8 + (tid >> 5);
        int cidx4 = (row << 8) + (col0 >> 2) + (tid & 31);  // float4 index
        float4 v  = xp[cidx4];
        int b0 = min(max((int)(fmaf(v.x, A, B) * 256.0f), 0), 255);
        int b1 = min(max((int)(fmaf(v.y, A, B) * 256.0f), 0), 255);
        int b2 = min(max((int)(fmaf(v.z, A, B) * 256.0f), 0), 255);
        int b3 = min(max((int)(fmaf(v.w, A, B) * 256.0f), 0), 255);
        atomicAdd(&h[wsub][b0], 1u);
        atomicAdd(&h[wsub][b1], 1u);
        atomicAdd(&h[wsub][b2], 1u);
        atomicAdd(&h[wsub][b3], 1u);
    }
    __syncthreads();

    unsigned int hv = 0;
#pragma unroll
    for (int k = 0; k < 8; k++) hv += h[k][tid];

    // clip + inclusive scan (Hillis-Steele) over 256 bins
    float v = fminf((float)hv, CLIPV);
    cs[tid] = v;
    __syncthreads();
#pragma unroll
    for (int off = 1; off < BINS; off <<= 1) {
        float add = (tid >= off) ? cs[tid - off] : 0.0f;
        __syncthreads();
        cs[tid] += add;
        __syncthreads();
    }
    float total = cs[BINS - 1];
    float resid = (16384.0f - total) * (1.0f / 256.0f);
    float lv = (cs[tid] + (float)(tid + 1) * resid) * (255.0f / 16384.0f);
    lv = floorf(fminf(fmaxf(lv, 0.0f), 255.0f));
    g_lut8[t * BINS + tid] = (unsigned char)lv;
}

// ---------------------------------------------------------------------------
// Kernel 3: bilinear LUT apply — recomputes the bin from x (byte-identical
// expression to k_hist; x is L2-resident), ONE LDS.32 per pixel, x[g] load
// software-pipelined one iteration ahead.
// ---------------------------------------------------------------------------
__device__ __forceinline__ float u8f(unsigned int packed, int sel)
{
    // byte -> float via exponent-bias trick: 0x4B0000vv = 8388608 + vv
    return __int_as_float(__byte_perm(packed, 0x4B000000, sel)) - 8388608.0f;
}

__global__ void __launch_bounds__(256) k_apply(const float4* __restrict__ x,
                                               float4* __restrict__ out)
{
    __shared__ unsigned int slut[8 * BINS];   // 8 KB

    int blk  = blockIdx.x;          // 0..2047
    int bc   = blk >> 7;            // image
    int seg  = blk & 127;           // 8-row segment
    int band = seg >> 3;            // 64-row band (0..15)
    int i0   = (band == 0) ? 0 : ((band - 1) >> 1);
    int i1   = min(i0 + 1, 7);

    const unsigned char* lb = g_lut8 + ((size_t)bc << 6) * BINS;
#pragma unroll
    for (int s = threadIdx.x; s < 8 * BINS; s += 256) {
        int j0 = s >> 8, b = s & 255;
        int j1 = min(j0 + 1, 7);
        unsigned int v00 = lb[(((i0 << 3) + j0) << 8) + b];
        unsigned int v10 = lb[(((i1 << 3) + j0) << 8) + b];
        unsigned int v01 = lb[(((i0 << 3) + j1) << 8) + b];
        unsigned int v11 = lb[(((i1 << 3) + j1) << 8) + b];
        slut[s] = v00 | (v10 << 8) | (v01 << 16) | (v11 << 24);
    }
    __syncthreads();

    float A = g_AB[0], B = g_AB[1];
    int tid = threadIdx.x;          // == col4 (float4 column), each it = 1 row

    // per-thread loop-invariant x-interpolation setup (4 pixels)
    float wx[4];
    int   jb[4];                    // (j0 << 8), ready to add bin
#pragma unroll
    for (int p = 0; p < 4; p++) {
        int   col = (tid << 2) + p;
        float gj  = fminf(fmaxf((col + 0.5f) * (1.0f / 128.0f) - 0.5f, 0.0f), 7.0f);
        int   j0  = (int)gj;
        wx[p] = gj - (float)j0;
        jb[p] = j0 << 8;
    }

    int row_base = seg << 3;                                // first row (8 rows)
    int f4_base  = (bc << 18) + (row_base << 8) + tid;      // float4 index

    float4 v = x[f4_base];                                  // prologue load
#pragma unroll
    for (int it = 0; it < 8; it++) {
        float4 vn;
        if (it < 7) vn = x[f4_base + ((it + 1) << 8)];      // prefetch next row

        int   row = row_base + it;
        float gi  = fminf(fmaxf((row + 0.5f) * (1.0f / 128.0f) - 0.5f, 0.0f), 7.0f);
        float wy  = gi - (float)i0;

        int bs[4];
        bs[0] = min(max((int)(fmaf(v.x, A, B) * 256.0f), 0), 255);
        bs[1] = min(max((int)(fmaf(v.y, A, B) * 256.0f), 0), 255);
        bs[2] = min(max((int)(fmaf(v.z, A, B) * 256.0f), 0), 255);
        bs[3] = min(max((int)(fmaf(v.w, A, B) * 256.0f), 0), 255);

        float r[4];
#pragma unroll
        for (int p = 0; p < 4; p++) {
            unsigned int packed = slut[jb[p] + bs[p]];
            float v00 = u8f(packed, 0x7440);
            float v10 = u8f(packed, 0x7441);
            float v01 = u8f(packed, 0x7442);
            float v11 = u8f(packed, 0x7443);
            float top = fmaf(wx[p], v01 - v00, v00);
            float bot = fmaf(wx[p], v11 - v10, v10);
            r[p] = fmaf(wy, bot - top, top) * (1.0f / 255.0f);
        }
        __stcs(&out[f4_base + (it << 8)], make_float4(r[0], r[1], r[2], r[3]));
        v = vn;
    }
}

extern "C" void kernel_launch(void* const* d_in, const int* in_sizes, int n_in,
                              void* d_out, int out_size)
{
    const float* x   = (const float*)d_in[0];
    const int*   y   = (n_in >= 2) ? (const int*)d_in[1] : nullptr;
    float*       out = (float*)d_out;

    int tail = out_size - N_PIX;
    if (tail < 0) tail = 0;

    k_reduce<<<RED_B, 256>>>((const float4*)x, y, out + N_PIX, tail);
    k_hist  <<<TILES, 256>>>(x);
    k_apply <<<2048, 256>>>((const float4*)x, (float4*)out);
}

// round 11
// speedup vs baseline: 1.1500x; 1.0943x over previous
#include <cuda_runtime.h>
#include <cstdint>
#include <cfloat>

// Problem constants
#define N_PIX   16777216          // 16 * 1 * 1024 * 1024
#define NF4     4194304           // N_PIX / 4
#define RB      1024              // reduction blocks
#define BINS    256
#define TILES   1024              // 16 images * 8 * 8
#define CLIPV   2560.0f           // max(int(40.0*16384//256),1)

// Scratch (device globals only — no allocations allowed)
__device__ float         g_pmin[RB];
__device__ float         g_pmax[RB];
__device__ double        g_psum[RB];
__device__ double        g_psq [RB];
__device__ float         g_AB[2];
__device__ unsigned int  g_ctr = 0;
__device__ unsigned char g_lut8[TILES * BINS];   // LUT values are exact ints 0..255

__device__ __forceinline__ unsigned int smem_u32(const void* p)
{
    unsigned int a;
    asm("{ .reg .u64 t; cvta.to.shared.u64 t, %1; cvt.u32.u64 %0, t; }"
        : "=r"(a) : "l"(p));
    return a;
}

// ---------------------------------------------------------------------------
// Kernel 1: streaming min/max/sum/sumsq. 1024 blocks x 256 thr x 16 chunks,
// 8-stage cp.async ring: loads stream continuously while older chunks are
// reduced (DRAM never idles on compute). Per-thread fp32 accumulation, warp-
// shuffle reduce, fp64 only at the 8-warp fold. Last block (fence + ticket)
// folds the 1024 partials, computes affine constants A,B, writes the y tail.
// ---------------------------------------------------------------------------
__global__ void __launch_bounds__(256) k_reduce(const float4* __restrict__ x,
                                                const int* __restrict__ y,
                                                float* __restrict__ tail_dst,
                                                int tail_n)
{
    __shared__ float4 sbuf[8 * 256];        // 32 KB ring (8 stages)
    __shared__ float  wmn[8], wmx[8];
    __shared__ double wss[8], wsq[8];

    int tid  = threadIdx.x;
    int lane = tid & 31;
    int wid  = tid >> 5;
    int t    = blockIdx.x * 256 + tid;

    float mn =  FLT_MAX, mx = -FLT_MAX;
    float s = 0.0f, q = 0.0f;

#define ISSUE(c) { \
        unsigned int dst = smem_u32(&sbuf[((c) & 7) * 256 + tid]); \
        const float4* src = x + t + (c) * (RB * 256); \
        asm volatile("cp.async.cg.shared.global [%0], [%1], 16;" :: "r"(dst), "l"(src)); \
        asm volatile("cp.async.commit_group;"); }

#define CONSUME(c, W) { \
        asm volatile("cp.async.wait_group " #W ";" ::: "memory"); \
        float4 v = sbuf[((c) & 7) * 256 + tid]; \
        mn = fminf(mn, fminf(fminf(v.x, v.y), fminf(v.z, v.w))); \
        mx = fmaxf(mx, fmaxf(fmaxf(v.x, v.y), fmaxf(v.z, v.w))); \
        s += (v.x + v.y) + (v.z + v.w); \
        q += (v.x * v.x + v.y * v.y) + (v.z * v.z + v.w * v.w); }

    // prologue: fill the ring
    ISSUE(0) ISSUE(1) ISSUE(2) ISSUE(3) ISSUE(4) ISSUE(5) ISSUE(6) ISSUE(7)
    // steady state: consume c, issue c+8
    CONSUME(0, 7)  ISSUE(8)
    CONSUME(1, 7)  ISSUE(9)
    CONSUME(2, 7)  ISSUE(10)
    CONSUME(3, 7)  ISSUE(11)
    CONSUME(4, 7)  ISSUE(12)
    CONSUME(5, 7)  ISSUE(13)
    CONSUME(6, 7)  ISSUE(14)
    CONSUME(7, 7)  ISSUE(15)
    // drain
    CONSUME(8, 7)
    CONSUME(9, 6)
    CONSUME(10, 5)
    CONSUME(11, 4)
    CONSUME(12, 3)
    CONSUME(13, 2)
    CONSUME(14, 1)
    CONSUME(15, 0)
#undef ISSUE
#undef CONSUME

    // warp shuffle reduction (fp32)
#pragma unroll
    for (int o = 16; o > 0; o >>= 1) {
        mn = fminf(mn, __shfl_xor_sync(0xFFFFFFFFu, mn, o));
        mx = fmaxf(mx, __shfl_xor_sync(0xFFFFFFFFu, mx, o));
        s += __shfl_xor_sync(0xFFFFFFFFu, s, o);
        q += __shfl_xor_sync(0xFFFFFFFFu, q, o);
    }
    if (lane == 0) {
        wmn[wid] = mn; wmx[wid] = mx;
        wss[wid] = (double)s; wsq[wid] = (double)q;
    }
    __syncthreads();

    // warp 0 folds the 8 warp partials (fp64 sums)
    if (wid == 0) {
        float  fmn = (lane < 8) ? wmn[lane] :  FLT_MAX;
        float  fmx = (lane < 8) ? wmx[lane] : -FLT_MAX;
        double ds  = (lane < 8) ? wss[lane] : 0.0;
        double dq  = (lane < 8) ? wsq[lane] : 0.0;
#pragma unroll
        for (int o = 4; o > 0; o >>= 1) {
            fmn = fminf(fmn, __shfl_xor_sync(0xFFFFFFFFu, fmn, o));
            fmx = fmaxf(fmx, __shfl_xor_sync(0xFFFFFFFFu, fmx, o));
            ds += __shfl_xor_sync(0xFFFFFFFFu, ds, o);
            dq += __shfl_xor_sync(0xFFFFFFFFu, dq, o);
        }
        if (lane == 0) {
            g_pmin[blockIdx.x] = fmn;
            g_pmax[blockIdx.x] = fmx;
            g_psum[blockIdx.x] = ds;
            g_psq [blockIdx.x] = dq;
        }
    }

    // ---- last-block-done: finalize + tail ----
    __shared__ bool is_last;
    __threadfence();
    if (tid == 0) {
        unsigned int ticket = atomicAdd(&g_ctr, 1u);
        is_last = (ticket == RB - 1);
    }
    __syncthreads();
    if (!is_last) return;

    __shared__ float  smn2[256], smx2[256];
    __shared__ double ss2[256], sq2[256];
    {
        float  lmn =  FLT_MAX, lmx = -FLT_MAX;
        double ls = 0.0, lq = 0.0;
#pragma unroll
        for (int i = 0; i < 4; i++) {
            int k = tid + i * 256;
            lmn = fminf(lmn, g_pmin[k]);
            lmx = fmaxf(lmx, g_pmax[k]);
            ls += g_psum[k];
            lq += g_psq[k];
        }
        smn2[tid] = lmn; smx2[tid] = lmx; ss2[tid] = ls; sq2[tid] = lq;
    }
    __syncthreads();
    for (int o = 128; o > 0; o >>= 1) {
        if (tid < o) {
            smn2[tid] = fminf(smn2[tid], smn2[tid + o]);
            smx2[tid] = fmaxf(smx2[tid], smx2[tid + o]);
            ss2[tid] += ss2[tid + o];
            sq2[tid] += sq2[tid + o];
        }
        __syncthreads();
    }
    if (tid == 0) {
        double mn2 = (double)smn2[0];
        double mx2 = (double)smx2[0];
        double span = mx2 - mn2;
        const double N = (double)N_PIX;
        double S = ss2[0], Q = sq2[0];
        double meanx = S / N;
        double varx  = (Q - S * S / N) / (N - 1.0);
        double mean1 = (meanx - mn2) / span;
        double std1  = sqrt(varx) / span;
        double zmin  = (0.0 - mean1) / std1;
        double zmax  = (1.0 - mean1) / std1;
        double zspan = zmax - zmin;
        double A = 1.0 / (span * std1 * zspan);
        double B = (((0.0 - mn2) / span - mean1) / std1 - zmin) / zspan;
        g_AB[0] = (float)A;
        g_AB[1] = (float)B;
        g_ctr = 0;                 // reset for next graph replay
    }
    // y tail: numeric float32 conversion (y is int32)
    if (tid < tail_n) tail_dst[tid] = (float)y[tid];
}

// ---------------------------------------------------------------------------
// Kernel 2: one 256-thread block per 128x128 tile. 8 warp-private
// sub-histograms (no bidx store), then clip -> scan -> residual -> LUT.
// x is L2-resident after k_reduce streamed it.
// ---------------------------------------------------------------------------
__global__ void __launch_bounds__(256) k_hist(const float* __restrict__ x)
{
    __shared__ unsigned int h[8][BINS];
    __shared__ float        cs[BINS];

    int t   = blockIdx.x;          // tile id: ((bc*8)+ti)*8+tj
    int tid = threadIdx.x;
#pragma unroll
    for (int k = 0; k < 8; k++) h[k][tid] = 0;
    __syncthreads();

    float A = g_AB[0], B = g_AB[1];

    int bc = t >> 6;
    int ti = (t >> 3) & 7;
    int tj = t & 7;
    int row0 = ti * 128;
    int col0 = tj * 128;
    int wsub = tid >> 5;           // warp-private sub-histogram

    const float4* xp = (const float4*)(x + ((size_t)bc << 20));

#pragma unroll
    for (int it = 0; it < 16; it++) {
        int row   = row0 + it * 8 + (tid >> 5);
        int cidx4 = (row << 8) + (col0 >> 2) + (tid & 31);  // float4 index
        float4 v  = xp[cidx4];
        int b0 = min(max((int)(fmaf(v.x, A, B) * 256.0f), 0), 255);
        int b1 = min(max((int)(fmaf(v.y, A, B) * 256.0f), 0), 255);
        int b2 = min(max((int)(fmaf(v.z, A, B) * 256.0f), 0), 255);
        int b3 = min(max((int)(fmaf(v.w, A, B) * 256.0f), 0), 255);
        atomicAdd(&h[wsub][b0], 1u);
        atomicAdd(&h[wsub][b1], 1u);
        atomicAdd(&h[wsub][b2], 1u);
        atomicAdd(&h[wsub][b3], 1u);
    }
    __syncthreads();

    unsigned int hv = 0;
#pragma unroll
    for (int k = 0; k < 8; k++) hv += h[k][tid];

    // clip + inclusive scan (Hillis-Steele) over 256 bins
    float v = fminf((float)hv, CLIPV);
    cs[tid] = v;
    __syncthreads();
#pragma unroll
    for (int off = 1; off < BINS; off <<= 1) {
        float add = (tid >= off) ? cs[tid - off] : 0.0f;
        __syncthreads();
        cs[tid] += add;
        __syncthreads();
    }
    float total = cs[BINS - 1];
    float resid = (16384.0f - total) * (1.0f / 256.0f);
    float lv = (cs[tid] + (float)(tid + 1) * resid) * (255.0f / 16384.0f);
    lv = floorf(fminf(fmaxf(lv, 0.0f), 255.0f));
    g_lut8[t * BINS + tid] = (unsigned char)lv;
}

// ---------------------------------------------------------------------------
// Kernel 3: bilinear LUT apply — recomputes the bin from x (byte-identical
// expression to k_hist; x is L2-resident), ONE LDS.32 per pixel, x[g] load
// software-pipelined one iteration ahead.
// ---------------------------------------------------------------------------
__device__ __forceinline__ float u8f(unsigned int packed, int sel)
{
    // byte -> float via exponent-bias trick: 0x4B0000vv = 8388608 + vv
    return __int_as_float(__byte_perm(packed, 0x4B000000, sel)) - 8388608.0f;
}

__global__ void __launch_bounds__(256) k_apply(const float4* __restrict__ x,
                                               float4* __restrict__ out)
{
    __shared__ unsigned int slut[8 * BINS];   // 8 KB

    int blk  = blockIdx.x;          // 0..2047
    int bc   = blk >> 7;            // image
    int seg  = blk & 127;           // 8-row segment
    int band = seg >> 3;            // 64-row band (0..15)
    int i0   = (band == 0) ? 0 : ((band - 1) >> 1);
    int i1   = min(i0 + 1, 7);

    const unsigned char* lb = g_lut8 + ((size_t)bc << 6) * BINS;
#pragma unroll
    for (int s = threadIdx.x; s < 8 * BINS; s += 256) {
        int j0 = s >> 8, b = s & 255;
        int j1 = min(j0 + 1, 7);
        unsigned int v00 = lb[(((i0 << 3) + j0) << 8) + b];
        unsigned int v10 = lb[(((i1 << 3) + j0) << 8) + b];
        unsigned int v01 = lb[(((i0 << 3) + j1) << 8) + b];
        unsigned int v11 = lb[(((i1 << 3) + j1) << 8) + b];
        slut[s] = v00 | (v10 << 8) | (v01 << 16) | (v11 << 24);
    }
    __syncthreads();

    float A = g_AB[0], B = g_AB[1];
    int tid = threadIdx.x;          // == col4 (float4 column), each it = 1 row

    // per-thread loop-invariant x-interpolation setup (4 pixels)
    float wx[4];
    int   jb[4];                    // (j0 << 8), ready to add bin
#pragma unroll
    for (int p = 0; p < 4; p++) {
        int   col = (tid << 2) + p;
        float gj  = fminf(fmaxf((col + 0.5f) * (1.0f / 128.0f) - 0.5f, 0.0f), 7.0f);
        int   j0  = (int)gj;
        wx[p] = gj - (float)j0;
        jb[p] = j0 << 8;
    }

    int row_base = seg << 3;                                // first row (8 rows)
    int f4_base  = (bc << 18) + (row_base << 8) + tid;      // float4 index

    float4 v = x[f4_base];                                  // prologue load
#pragma unroll
    for (int it = 0; it < 8; it++) {
        float4 vn;
        if (it < 7) vn = x[f4_base + ((it + 1) << 8)];      // prefetch next row

        int   row = row_base + it;
        float gi  = fminf(fmaxf((row + 0.5f) * (1.0f / 128.0f) - 0.5f, 0.0f), 7.0f);
        float wy  = gi - (float)i0;

        int bs[4];
        bs[0] = min(max((int)(fmaf(v.x, A, B) * 256.0f), 0), 255);
        bs[1] = min(max((int)(fmaf(v.y, A, B) * 256.0f), 0), 255);
        bs[2] = min(max((int)(fmaf(v.z, A, B) * 256.0f), 0), 255);
        bs[3] = min(max((int)(fmaf(v.w, A, B) * 256.0f), 0), 255);

        float r[4];
#pragma unroll
        for (int p = 0; p < 4; p++) {
            unsigned int packed = slut[jb[p] + bs[p]];
            float v00 = u8f(packed, 0x7440);
            float v10 = u8f(packed, 0x7441);
            float v01 = u8f(packed, 0x7442);
            float v11 = u8f(packed, 0x7443);
            float top = fmaf(wx[p], v01 - v00, v00);
            float bot = fmaf(wx[p], v11 - v10, v10);
            r[p] = fmaf(wy, bot - top, top) * (1.0f / 255.0f);
        }
        __stcs(&out[f4_base + (it << 8)], make_float4(r[0], r[1], r[2], r[3]));
        v = vn;
    }
}

extern "C" void kernel_launch(void* const* d_in, const int* in_sizes, int n_in,
                              void* d_out, int out_size)
{
    const float* x   = (const float*)d_in[0];
    const int*   y   = (n_in >= 2) ? (const int*)d_in[1] : nullptr;
    float*       out = (float*)d_out;

    int tail = out_size - N_PIX;
    if (tail < 0) tail = 0;

    k_reduce<<<RB, 256>>>((const float4*)x, y, out + N_PIX, tail);
    k_hist  <<<TILES, 256>>>(x);
    k_apply <<<2048, 256>>>((const float4*)x, (float4*)out);
}